// round 13
// baseline (speedup 1.0000x reference)
#include <cuda_runtime.h>
#include <cuda_fp16.h>
#include <cstdint>

typedef __half h16;
#define B_SZ  16384
#define IN_SZ 768
#define H_SZ  1024

// ---------------- scratch ----------------
__device__ h16 g_Th[(size_t)B_SZ * 512];
__device__ h16 g_Tl[(size_t)B_SZ * 512];
__device__ h16 g_W1x[256 * IN_SZ];
__device__ h16 g_W1h[256 * H_SZ];
__device__ h16 g_W2[(size_t)4 * H_SZ * 128];
__device__ float g_aw[4][IN_SZ];
__device__ float g_bu[4][H_SZ];

// ---------------- helpers ----------------
__device__ __forceinline__ uint32_t smem_u32(const void* p) {
    uint32_t a;
    asm("{ .reg .u64 t; cvta.to.shared.u64 t, %1; cvt.u32.u64 %0, t; }" : "=r"(a) : "l"(p));
    return a;
}
__device__ __forceinline__ void ldsm4(uint32_t (&r)[4], uint32_t a) {
    asm volatile("ldmatrix.sync.aligned.m8n8.x4.shared.b16 {%0,%1,%2,%3}, [%4];"
                 : "=r"(r[0]), "=r"(r[1]), "=r"(r[2]), "=r"(r[3]) : "r"(a));
}
__device__ __forceinline__ void mma_f16(float (&c)[4], const uint32_t (&a)[4],
                                        uint32_t b0, uint32_t b1) {
    asm volatile(
        "mma.sync.aligned.m16n8k16.row.col.f32.f16.f16.f32 "
        "{%0,%1,%2,%3},{%4,%5,%6,%7},{%8,%9},{%0,%1,%2,%3};"
        : "+f"(c[0]), "+f"(c[1]), "+f"(c[2]), "+f"(c[3])
        : "r"(a[0]), "r"(a[1]), "r"(a[2]), "r"(a[3]), "r"(b0), "r"(b1));
}
#define CP16(s, g) asm volatile("cp.async.cg.shared.global [%0], [%1], 16;" :: "r"(s), "l"(g))
#define CPC()      asm volatile("cp.async.commit_group;")
template <int N> __device__ __forceinline__ void cpwait() {
    asm volatile("cp.async.wait_group %0;" :: "n"(N));
}
__device__ __forceinline__ uint32_t pack_h2(float a, float b) {
    h16 ha = __float2half_rn(a), hb = __float2half_rn(b);
    return (uint32_t)__half_as_ushort(ha) | ((uint32_t)__half_as_ushort(hb) << 16);
}
__device__ __forceinline__ void split_pack(float a, float b, uint32_t& hi, uint32_t& lo) {
    h16 ha = __float2half_rn(a), hb = __float2half_rn(b);
    h16 la = __float2half_rn(a - __half2float(ha));
    h16 lb = __float2half_rn(b - __half2float(hb));
    hi = (uint32_t)__half_as_ushort(ha) | ((uint32_t)__half_as_ushort(hb) << 16);
    lo = (uint32_t)__half_as_ushort(la) | ((uint32_t)__half_as_ushort(lb) << 16);
}
__device__ __forceinline__ const float* sel4(int g, const float* a, const float* b,
                                             const float* c, const float* d) {
    return g == 0 ? a : g == 1 ? b : g == 2 ? c : d;
}
__device__ __forceinline__ float sigf(float z) {
    z = fminf(fmaxf(z, -30.f), 30.f);
    return 1.f / (1.f + __expf(-z));
}
__device__ __forceinline__ float tanhfast(float z) {
    z = fminf(fmaxf(z, -15.f), 15.f);
    float e = __expf(-2.f * z);
    return (1.f - e) / (1.f + e);
}

// ---------------- preps (unchanged) ----------------
__global__ void prep_w1t(const float* __restrict__ F0, const float* __restrict__ F1,
                         const float* __restrict__ F2, const float* __restrict__ F3,
                         int K, h16* __restrict__ D) {
    __shared__ float t[32][33];
    int k0 = blockIdx.x * 32, nt = blockIdx.y;
    int g = nt >> 1, r0 = (nt & 1) * 32;
    const float* F = sel4(g, F0, F1, F2, F3);
    int tx = threadIdx.x & 31, ty = threadIdx.x >> 5;
#pragma unroll
    for (int i = 0; i < 4; ++i)
        t[ty + i * 8][tx] = F[(size_t)(k0 + ty + i * 8) * 64 + r0 + tx];
    __syncthreads();
#pragma unroll
    for (int i = 0; i < 4; ++i) {
        int row = ty + i * 8;
        int n = nt * 32 + row, k = k0 + tx;
        D[(size_t)n * K + k] = __float2half_rn(t[tx][row]);
    }
}

__global__ void prep_w2t(const float* __restrict__ Wf, const float* __restrict__ Wi,
                         const float* __restrict__ Wc, const float* __restrict__ Wo,
                         const float* __restrict__ Uf, const float* __restrict__ Ui,
                         const float* __restrict__ Uc, const float* __restrict__ Uo) {
    __shared__ float t[32][33];
    int k0 = blockIdx.x * 32, n0 = blockIdx.y * 32, g = blockIdx.z;
    const float* S = (k0 < 64) ? sel4(g, Wf, Wi, Wc, Wo) : sel4(g, Uf, Ui, Uc, Uo);
    int kr0 = (k0 < 64) ? k0 : k0 - 64;
    int tx = threadIdx.x & 31, ty = threadIdx.x >> 5;
#pragma unroll
    for (int i = 0; i < 4; ++i)
        t[ty + i * 8][tx] = S[(size_t)(kr0 + ty + i * 8) * H_SZ + n0 + tx];
    __syncthreads();
#pragma unroll
    for (int i = 0; i < 4; ++i) {
        int row = ty + i * 8;
        int n = n0 + row, k = k0 + tx;
        g_W2[((size_t)g * H_SZ + n) * 128 + k] = __float2half_rn(t[tx][row]);
    }
}

__global__ void prep_diag2(const float* __restrict__ Wu_f, const float* __restrict__ Wu_i,
                           const float* __restrict__ Wu_c, const float* __restrict__ Wu_o,
                           const float* __restrict__ Uu_f, const float* __restrict__ Uu_i,
                           const float* __restrict__ Uu_c, const float* __restrict__ Uu_o,
                           const float* __restrict__ Wf, const float* __restrict__ Wi,
                           const float* __restrict__ Wc, const float* __restrict__ Wo,
                           const float* __restrict__ Uf, const float* __restrict__ Ui,
                           const float* __restrict__ Uc, const float* __restrict__ Uo,
                           const float* __restrict__ W_dia, const float* __restrict__ U_dia) {
    __shared__ float fu[64][68];
    __shared__ float red[4][64];
    int b = blockIdx.x, tid = threadIdx.x;
    bool uside = (b < 64);
    int g, j0;
    const float *Fu, *Fv;
    if (uside) {
        g = b >> 4; j0 = (b & 15) * 64;
        Fu = sel4(g, Uu_f, Uu_i, Uu_c, Uu_o);
        Fv = sel4(g, Uf, Ui, Uc, Uo);
    } else {
        int t = b - 64;
        g = t / 12; j0 = (t % 12) * 64;
        Fu = sel4(g, Wu_f, Wu_i, Wu_c, Wu_o);
        Fv = sel4(g, Wf, Wi, Wc, Wo);
    }
#pragma unroll
    for (int i = 0; i < 4; ++i) {
        int id = tid + i * 256;
        int jj = id >> 4, rb = (id & 15) * 4;
        *(float4*)&fu[jj][rb] = *(const float4*)(Fu + (size_t)(j0 + jj) * 64 + rb);
    }
    __syncthreads();
    int jl = tid & 63, rq = tid >> 6;
    float s = 0.f;
#pragma unroll
    for (int i = 0; i < 16; ++i) {
        int r = rq * 16 + i;
        s += fu[jl][r] * Fv[(size_t)r * H_SZ + j0 + jl];
    }
    red[rq][jl] = s;
    __syncthreads();
    if (rq == 0) {
        float tot = red[0][jl] + red[1][jl] + red[2][jl] + red[3][jl];
        int j = j0 + jl;
        if (uside) g_bu[g][j] = U_dia[j] - tot;
        else       g_aw[g][j] = W_dia[j] - tot;
    }
}

// ---------------- GEMM1: m64 x n256, 256 thr, 2 CTAs/SM, 3 stages ----------------
// Stage (halves): A 0..2559 (64 rows x 40), B 2560..12799 (256 rows x 40). Stage 25600 B.
#define G1_SSTR 25600
#define G1_SMEM (3 * G1_SSTR)

__global__ __launch_bounds__(256, 2) void gemm1_hmma(
    const float* __restrict__ x, const float* __restrict__ hsrc,
    const h16* __restrict__ W1x, const h16* __restrict__ W1h) {
    extern __shared__ char smem[];
    h16* sp = (h16*)smem;
    const uint32_t sbase = smem_u32(smem);
    const int tid = threadIdx.x, wid = tid >> 5, lane = tid & 31;
    const int s = blockIdx.x, by = blockIdx.y;
    const float* A = s ? hsrc : x;
    const h16* B = s ? W1h : W1x;
    const int K = s ? H_SZ : IN_SZ;
    const int colOff = s * 64;
    const int NKT = K >> 5;
    const int nw = wid * 32;

    float acc[4][4][4];
#pragma unroll
    for (int a = 0; a < 4; ++a)
#pragma unroll
        for (int b = 0; b < 4; ++b)
#pragma unroll
            for (int q = 0; q < 4; ++q) acc[a][b][q] = 0.f;

    float4 aReg[2];
    auto fetchA = [&](int kt) {
#pragma unroll
        for (int i = 0; i < 2; ++i) {
            int id = tid + i * 256;
            int row = id >> 3, c4 = id & 7;
            aReg[i] = *(const float4*)(A + (size_t)(by * 64 + row) * K + kt * 32 + c4 * 4);
        }
    };
    auto stsA = [&](int st) {
        h16* d = sp + st * (G1_SSTR / 2);
#pragma unroll
        for (int i = 0; i < 2; ++i) {
            int id = tid + i * 256;
            int row = id >> 3, c4 = id & 7;
            uint32_t h01 = pack_h2(aReg[i].x, aReg[i].y);
            uint32_t h23 = pack_h2(aReg[i].z, aReg[i].w);
            *(uint2*)(d + row * 40 + c4 * 4) = make_uint2(h01, h23);
        }
    };
    auto cpB = [&](int kt, int st) {
        uint32_t sb = sbase + st * G1_SSTR;
#pragma unroll
        for (int i = 0; i < 4; ++i) {
            int id = tid + i * 256;
            int row = id >> 2, c = id & 3;
            size_t so = (size_t)row * K + kt * 32 + c * 8;
            uint32_t doff = (uint32_t)((2560 + row * 40 + c * 8) * 2);
            CP16(sb + doff, (const void*)(B + so));
        }
    };

    // prologue: stages 0 and 1 loaded, A regs for stage 2 prefetched
    fetchA(0); stsA(0); cpB(0, 0); CPC();
    fetchA(1); stsA(1); cpB(1, 1); CPC();
    if (NKT > 2) fetchA(2);

    for (int kt = 0; kt < NKT; ++kt) {
        int st = kt % 3;
        if (kt + 1 < NKT) cpwait<1>(); else cpwait<0>();
        __syncthreads();
        if (kt + 2 < NKT) {
            stsA((kt + 2) % 3);
            cpB(kt + 2, (kt + 2) % 3);
            CPC();
            if (kt + 3 < NKT) fetchA(kt + 3);
        }

        uint32_t sb = sbase + st * G1_SSTR;
#pragma unroll
        for (int ks = 0; ks < 2; ++ks) {
            uint32_t ah[4][4], bb[2][4];
            const int arow = (lane & 7) + ((lane >> 3) & 1) * 8;
            const int akc  = ks * 16 + (lane >> 4) * 8;
#pragma unroll
            for (int mf = 0; mf < 4; ++mf) {
                uint32_t ad = sb + (uint32_t)(((arow + mf * 16) * 40 + akc) * 2);
                ldsm4(ah[mf], ad);
            }
            const int bnr = nw + ((lane >> 4) << 3) + (lane & 7);
            const int bkc = ks * 16 + ((lane >> 3) & 1) * 8;
#pragma unroll
            for (int nh = 0; nh < 2; ++nh) {
                uint32_t bd = sb + (uint32_t)(((2560 + (bnr + nh * 16) * 40) + bkc) * 2);
                ldsm4(bb[nh], bd);
            }
#pragma unroll
            for (int mf = 0; mf < 4; ++mf)
#pragma unroll
                for (int nf = 0; nf < 4; ++nf) {
                    uint32_t b0 = bb[nf >> 1][(nf & 1) * 2], b1 = bb[nf >> 1][(nf & 1) * 2 + 1];
                    mma_f16(acc[mf][nf], ah[mf], b0, b1);
                }
        }
    }

#pragma unroll
    for (int mf = 0; mf < 4; ++mf)
#pragma unroll
        for (int nf = 0; nf < 4; ++nf) {
            int r0 = by * 64 + mf * 16 + (lane >> 2);
            int ncol = nw + nf * 8 + (lane & 3) * 2;
            int g = ncol >> 6;
            int tc = g * 128 + colOff + (ncol & 63);
            uint32_t hi, lo;
            split_pack(acc[mf][nf][0], acc[mf][nf][1], hi, lo);
            *(uint32_t*)&g_Th[(size_t)r0 * 512 + tc] = hi;
            *(uint32_t*)&g_Tl[(size_t)r0 * 512 + tc] = lo;
            split_pack(acc[mf][nf][2], acc[mf][nf][3], hi, lo);
            *(uint32_t*)&g_Th[(size_t)(r0 + 8) * 512 + tc] = hi;
            *(uint32_t*)&g_Tl[(size_t)(r0 + 8) * 512 + tc] = lo;
        }
}

// ---------------- GEMM2: m64 x n64 x 4g, 256 thr, 2 CTAs/SM, 3 stages ----------------
#define G2_HDR  3072
#define G2_SSTR 36864
#define G2_SMEM (G2_HDR + 3 * G2_SSTR)   // 113664 -> 2 CTAs/SM

__global__ __launch_bounds__(256, 2) void gemm2_hmma(
    const float* __restrict__ x, const float* __restrict__ h, const float* __restrict__ c,
    const float* __restrict__ bias_f, const float* __restrict__ bias_i,
    const float* __restrict__ bias_c, const float* __restrict__ bias_o,
    float* __restrict__ out) {
    extern __shared__ char smem[];
    const uint32_t sbase = smem_u32(smem);
    const int tid = threadIdx.x, wid = tid >> 5, lane = tid & 31;
    const int bx = blockIdx.x, by = blockIdx.y;
    const int m0 = (wid & 3) * 16, n0w = (wid >> 2) * 32;

    float* ebias = (float*)smem;   // [4][64]
    float* ebu   = ebias + 256;
    float* eaw   = ebu + 256;
    {
        int g = tid >> 6, jl = tid & 63;
        int j = bx * 64 + jl;
        ebias[tid] = sel4(g, bias_f, bias_i, bias_c, bias_o)[j];
        ebu[tid]   = g_bu[g][j];
        eaw[tid]   = (j < IN_SZ) ? g_aw[g][j] : 0.f;
    }

    auto loadStage = [&](int kb, int st) {
        uint32_t sb = sbase + G2_HDR + st * G2_SSTR;
        const h16* Th = g_Th + (size_t)(by * 64) * 512 + kb * 16;
        const h16* Tl = g_Tl + (size_t)(by * 64) * 512 + kb * 16;
#pragma unroll
        for (int i = 0; i < 2; ++i) {
            int id = tid + i * 256;
            int g = id >> 7, rem = id & 127;
            int row = rem >> 1, cc = rem & 1;
            size_t so = (size_t)row * 512 + g * 128 + cc * 8;
            uint32_t doff = (uint32_t)(g * 3072 + row * 48 + cc * 16);
            CP16(sb + doff, (const void*)(Th + so));
            CP16(sb + 12288 + doff, (const void*)(Tl + so));
        }
#pragma unroll
        for (int i = 0; i < 2; ++i) {
            int id = tid + i * 256;
            int g = id >> 7, rem = id & 127;
            int n = rem >> 1, cc = rem & 1;
            size_t so = ((size_t)g * 1024 + bx * 64 + n) * 128 + kb * 16 + cc * 8;
            uint32_t doff = (uint32_t)(g * 3072 + n * 48 + cc * 16);
            CP16(sb + 24576 + doff, (const void*)(g_W2 + so));
        }
    };

    float acc[4][4][4];
#pragma unroll
    for (int a = 0; a < 4; ++a)
#pragma unroll
        for (int b = 0; b < 4; ++b)
#pragma unroll
            for (int q = 0; q < 4; ++q) acc[a][b][q] = 0.f;

    loadStage(0, 0); CPC();
    loadStage(1, 1); CPC();

    for (int kb = 0; kb < 8; ++kb) {
        int st = kb % 3;
        if (kb < 7) cpwait<1>(); else cpwait<0>();
        __syncthreads();
        if (kb + 2 < 8) {
            loadStage(kb + 2, (kb + 2) % 3);
            CPC();
        }

        uint32_t sb = sbase + G2_HDR + st * G2_SSTR;
        const int arow = m0 + (lane & 7) + ((lane >> 3) & 1) * 8;
        const int akc  = (lane >> 4) * 8;
        const int bnr = n0w + ((lane >> 4) << 3) + (lane & 7);
        const int bkc = ((lane >> 3) & 1) * 8;
#pragma unroll
        for (int g = 0; g < 4; ++g) {
            uint32_t ah[4], al[4], bb[2][4];
            uint32_t ad = sb + (uint32_t)(g * 3072 + arow * 48 + akc * 2);
            ldsm4(ah, ad);
            ldsm4(al, ad + 12288);
#pragma unroll
            for (int nh = 0; nh < 2; ++nh) {
                uint32_t bd = sb + (uint32_t)(24576 + g * 3072 + (bnr + nh * 16) * 48 + bkc * 2);
                ldsm4(bb[nh], bd);
            }
#pragma unroll
            for (int nf = 0; nf < 4; ++nf) {
                uint32_t b0 = bb[nf >> 1][(nf & 1) * 2], b1 = bb[nf >> 1][(nf & 1) * 2 + 1];
                mma_f16(acc[g][nf], ah, b0, b1);
                mma_f16(acc[g][nf], al, b0, b1);
            }
        }
    }

    // in-register LSTM epilogue
    const int r0 = m0 + (lane >> 2);
    const int jcb = n0w + (lane & 3) * 2;
    const bool hasx = (bx * 64 < IN_SZ);
    const size_t GS = (size_t)B_SZ * H_SZ;
#pragma unroll
    for (int nf = 0; nf < 4; ++nf) {
        int jl = jcb + nf * 8;
        int j = bx * 64 + jl;
#pragma unroll
        for (int rr = 0; rr < 2; ++rr) {
            int b = by * 64 + r0 + rr * 8;
            float2 h2 = *(const float2*)(h + (size_t)b * 1024 + j);
            float2 c2 = *(const float2*)(c + (size_t)b * 1024 + j);
            float2 x2 = hasx ? *(const float2*)(x + (size_t)b * IN_SZ + j) : make_float2(0.f, 0.f);
            float pr[4][2];
#pragma unroll
            for (int g = 0; g < 4; ++g) {
                pr[g][0] = acc[g][nf][rr * 2 + 0] + ebias[g * 64 + jl]     + h2.x * ebu[g * 64 + jl]     + x2.x * eaw[g * 64 + jl];
                pr[g][1] = acc[g][nf][rr * 2 + 1] + ebias[g * 64 + jl + 1] + h2.y * ebu[g * 64 + jl + 1] + x2.y * eaw[g * 64 + jl + 1];
            }
            float2 hn, cn;
            {
                float f = sigf(pr[0][0]), ii = sigf(pr[1][0]), gg = tanhfast(pr[2][0]), o = sigf(pr[3][0]);
                cn.x = f * c2.x + ii * gg;
                hn.x = o * tanhfast(cn.x);
            }
            {
                float f = sigf(pr[0][1]), ii = sigf(pr[1][1]), gg = tanhfast(pr[2][1]), o = sigf(pr[3][1]);
                cn.y = f * c2.y + ii * gg;
                hn.y = o * tanhfast(cn.y);
            }
            *(float2*)(out + (size_t)b * 1024 + j)      = hn;
            *(float2*)(out + GS + (size_t)b * 1024 + j) = cn;
        }
    }
}

// ---------------- launch ----------------
extern "C" void kernel_launch(void* const* d_in, const int* in_sizes, int n_in,
                              void* d_out, int out_size) {
    const float* x = (const float*)d_in[0];
    const float* h = (const float*)d_in[1];
    const float* c = (const float*)d_in[2];
    const float* Wu_f = (const float*)d_in[3];
    const float* Wu_i = (const float*)d_in[4];
    const float* Wu_c = (const float*)d_in[5];
    const float* Wu_o = (const float*)d_in[6];
    const float* Uu_f = (const float*)d_in[7];
    const float* Uu_i = (const float*)d_in[8];
    const float* Uu_c = (const float*)d_in[9];
    const float* Uu_o = (const float*)d_in[10];
    const float* Wf = (const float*)d_in[11];
    const float* Wi = (const float*)d_in[12];
    const float* Wc = (const float*)d_in[13];
    const float* Wo = (const float*)d_in[14];
    const float* Uf = (const float*)d_in[15];
    const float* Ui = (const float*)d_in[16];
    const float* Uc = (const float*)d_in[17];
    const float* Uo = (const float*)d_in[18];
    const float* bias_f = (const float*)d_in[19];
    const float* bias_i = (const float*)d_in[20];
    const float* bias_c = (const float*)d_in[21];
    const float* bias_o = (const float*)d_in[22];
    const float* W_dia = (const float*)d_in[23];
    const float* U_dia = (const float*)d_in[24];
    float* out = (float*)d_out;

    h16 *pW1x, *pW1h;
    cudaGetSymbolAddress((void**)&pW1x, g_W1x);
    cudaGetSymbolAddress((void**)&pW1h, g_W1h);

    cudaFuncSetAttribute(gemm1_hmma, cudaFuncAttributeMaxDynamicSharedMemorySize, G1_SMEM);
    cudaFuncSetAttribute(gemm2_hmma, cudaFuncAttributeMaxDynamicSharedMemorySize, G2_SMEM);

    prep_w1t<<<dim3(IN_SZ / 32, 8), 256>>>(Wu_f, Wu_i, Wu_c, Wu_o, IN_SZ, pW1x);
    prep_w1t<<<dim3(H_SZ / 32, 8), 256>>>(Uu_f, Uu_i, Uu_c, Uu_o, H_SZ, pW1h);
    prep_w2t<<<dim3(4, 32, 4), 256>>>(Wf, Wi, Wc, Wo, Uf, Ui, Uc, Uo);
    prep_diag2<<<112, 256>>>(Wu_f, Wu_i, Wu_c, Wu_o, Uu_f, Uu_i, Uu_c, Uu_o,
                             Wf, Wi, Wc, Wo, Uf, Ui, Uc, Uo, W_dia, U_dia);

    gemm1_hmma<<<dim3(2, B_SZ / 64), 256, G1_SMEM>>>(x, h, pW1x, pW1h);

    gemm2_hmma<<<dim3(H_SZ / 64, B_SZ / 64), 256, G2_SMEM>>>(
        x, h, c, bias_f, bias_i, bias_c, bias_o, out);
}

// round 14
// speedup vs baseline: 1.0586x; 1.0586x over previous
#include <cuda_runtime.h>
#include <cuda_fp16.h>
#include <cstdint>

typedef __half h16;
#define B_SZ  16384
#define IN_SZ 768
#define H_SZ  1024

// ---------------- scratch ----------------
__device__ h16 g_Th[(size_t)B_SZ * 512];
__device__ h16 g_Tl[(size_t)B_SZ * 512];
__device__ h16 g_W1x[256 * IN_SZ];
__device__ h16 g_W1h[256 * H_SZ];
__device__ h16 g_W2[(size_t)4 * H_SZ * 128];
__device__ float g_aw[4][IN_SZ];
__device__ float g_bu[4][H_SZ];

// ---------------- helpers ----------------
__device__ __forceinline__ uint32_t smem_u32(const void* p) {
    uint32_t a;
    asm("{ .reg .u64 t; cvta.to.shared.u64 t, %1; cvt.u32.u64 %0, t; }" : "=r"(a) : "l"(p));
    return a;
}
__device__ __forceinline__ void ldsm4(uint32_t (&r)[4], uint32_t a) {
    asm volatile("ldmatrix.sync.aligned.m8n8.x4.shared.b16 {%0,%1,%2,%3}, [%4];"
                 : "=r"(r[0]), "=r"(r[1]), "=r"(r[2]), "=r"(r[3]) : "r"(a));
}
__device__ __forceinline__ void mma_f16(float (&c)[4], const uint32_t (&a)[4],
                                        uint32_t b0, uint32_t b1) {
    asm volatile(
        "mma.sync.aligned.m16n8k16.row.col.f32.f16.f16.f32 "
        "{%0,%1,%2,%3},{%4,%5,%6,%7},{%8,%9},{%0,%1,%2,%3};"
        : "+f"(c[0]), "+f"(c[1]), "+f"(c[2]), "+f"(c[3])
        : "r"(a[0]), "r"(a[1]), "r"(a[2]), "r"(a[3]), "r"(b0), "r"(b1));
}
#define CP16(s, g) asm volatile("cp.async.cg.shared.global [%0], [%1], 16;" :: "r"(s), "l"(g))
#define CPC()      asm volatile("cp.async.commit_group;")
template <int N> __device__ __forceinline__ void cpwait() {
    asm volatile("cp.async.wait_group %0;" :: "n"(N));
}
__device__ __forceinline__ uint32_t pack_h2(float a, float b) {
    h16 ha = __float2half_rn(a), hb = __float2half_rn(b);
    return (uint32_t)__half_as_ushort(ha) | ((uint32_t)__half_as_ushort(hb) << 16);
}
__device__ __forceinline__ void split_pack(float a, float b, uint32_t& hi, uint32_t& lo) {
    h16 ha = __float2half_rn(a), hb = __float2half_rn(b);
    h16 la = __float2half_rn(a - __half2float(ha));
    h16 lb = __float2half_rn(b - __half2float(hb));
    hi = (uint32_t)__half_as_ushort(ha) | ((uint32_t)__half_as_ushort(hb) << 16);
    lo = (uint32_t)__half_as_ushort(la) | ((uint32_t)__half_as_ushort(lb) << 16);
}
__device__ __forceinline__ const float* sel4(int g, const float* a, const float* b,
                                             const float* c, const float* d) {
    return g == 0 ? a : g == 1 ? b : g == 2 ? c : d;
}
__device__ __forceinline__ float sigf(float z) {
    z = fminf(fmaxf(z, -30.f), 30.f);
    return 1.f / (1.f + __expf(-z));
}
__device__ __forceinline__ float tanhfast(float z) {
    z = fminf(fmaxf(z, -15.f), 15.f);
    float e = __expf(-2.f * z);
    return (1.f - e) / (1.f + e);
}

// ---------------- fused prep: all weight transposes + diag in ONE launch ----------------
// blocks: [0,192) W1x tiles, [192,448) W1h tiles, [448,960) W2 tiles, [960,1072) diag.
__global__ void prep_all(const float* __restrict__ Wu_f, const float* __restrict__ Wu_i,
                         const float* __restrict__ Wu_c, const float* __restrict__ Wu_o,
                         const float* __restrict__ Uu_f, const float* __restrict__ Uu_i,
                         const float* __restrict__ Uu_c, const float* __restrict__ Uu_o,
                         const float* __restrict__ Wf, const float* __restrict__ Wi,
                         const float* __restrict__ Wc, const float* __restrict__ Wo,
                         const float* __restrict__ Uf, const float* __restrict__ Ui,
                         const float* __restrict__ Uc, const float* __restrict__ Uo,
                         const float* __restrict__ W_dia, const float* __restrict__ U_dia) {
    __shared__ __align__(16) float buf[4608];   // 18432 B scratch union
    const int b = blockIdx.x, tid = threadIdx.x;
    const int tx = tid & 31, ty = tid >> 5;

    if (b < 448) {
        // ---- W1 transpose (x part: 192 blocks, h part: 256 blocks) ----
        const bool isx = (b < 192);
        const int bi = isx ? b : b - 192;
        const int K = isx ? IN_SZ : H_SZ;
        const int nkt = K >> 5;
        const int kt = bi % nkt, nt = bi / nkt;
        const int k0 = kt * 32;
        const int g = nt >> 1, r0 = (nt & 1) * 32;
        const float* F = isx ? sel4(g, Wu_f, Wu_i, Wu_c, Wu_o)
                             : sel4(g, Uu_f, Uu_i, Uu_c, Uu_o);
        h16* D = isx ? g_W1x : g_W1h;
        float (*t)[33] = (float(*)[33])buf;
#pragma unroll
        for (int i = 0; i < 4; ++i)
            t[ty + i * 8][tx] = F[(size_t)(k0 + ty + i * 8) * 64 + r0 + tx];
        __syncthreads();
#pragma unroll
        for (int i = 0; i < 4; ++i) {
            int row = ty + i * 8;
            int n = nt * 32 + row, k = k0 + tx;
            D[(size_t)n * K + k] = __float2half_rn(t[tx][row]);
        }
    } else if (b < 960) {
        // ---- W2 transpose: 512 blocks = 4 kt x 32 nt x 4 g ----
        const int i = b - 448;
        const int k0 = (i & 3) * 32, n0 = ((i >> 2) & 31) * 32, g = i >> 7;
        const float* S = (k0 < 64) ? sel4(g, Wf, Wi, Wc, Wo) : sel4(g, Uf, Ui, Uc, Uo);
        const int kr0 = (k0 < 64) ? k0 : k0 - 64;
        float (*t)[33] = (float(*)[33])buf;
#pragma unroll
        for (int q = 0; q < 4; ++q)
            t[ty + q * 8][tx] = S[(size_t)(kr0 + ty + q * 8) * H_SZ + n0 + tx];
        __syncthreads();
#pragma unroll
        for (int q = 0; q < 4; ++q) {
            int row = ty + q * 8;
            int n = n0 + row, k = k0 + tx;
            g_W2[((size_t)g * H_SZ + n) * 128 + k] = __float2half_rn(t[tx][row]);
        }
    } else {
        // ---- diag corrections: 112 blocks (64 U-side, 48 W-side) ----
        const int bb = b - 960;
        const bool uside = (bb < 64);
        int g, j0;
        const float *Fu, *Fv;
        if (uside) {
            g = bb >> 4; j0 = (bb & 15) * 64;
            Fu = sel4(g, Uu_f, Uu_i, Uu_c, Uu_o);
            Fv = sel4(g, Uf, Ui, Uc, Uo);
        } else {
            int t2 = bb - 64;
            g = t2 / 12; j0 = (t2 % 12) * 64;
            Fu = sel4(g, Wu_f, Wu_i, Wu_c, Wu_o);
            Fv = sel4(g, Wf, Wi, Wc, Wo);
        }
        float (*fu)[68] = (float(*)[68])buf;            // 64*68 = 4352 floats
        float (*red)[64] = (float(*)[64])(buf + 4352);  // 4*64 = 256 floats
#pragma unroll
        for (int i = 0; i < 4; ++i) {
            int id = tid + i * 256;
            int jj = id >> 4, rb = (id & 15) * 4;
            *(float4*)&fu[jj][rb] = *(const float4*)(Fu + (size_t)(j0 + jj) * 64 + rb);
        }
        __syncthreads();
        int jl = tid & 63, rq = tid >> 6;
        float s = 0.f;
#pragma unroll
        for (int i = 0; i < 16; ++i) {
            int r = rq * 16 + i;
            s += fu[jl][r] * Fv[(size_t)r * H_SZ + j0 + jl];
        }
        red[rq][jl] = s;
        __syncthreads();
        if (rq == 0) {
            float tot = red[0][jl] + red[1][jl] + red[2][jl] + red[3][jl];
            int j = j0 + jl;
            if (uside) g_bu[g][j] = U_dia[j] - tot;
            else       g_aw[g][j] = W_dia[j] - tot;
        }
    }
}

// ---------------- GEMM1: m64 x n256, 256 thr, 2 CTAs/SM, 2 stages, single-sync (R12) ----------------
#define G1_SSTR 25600
#define G1_SMEM (2 * G1_SSTR)

__global__ __launch_bounds__(256, 2) void gemm1_hmma(
    const float* __restrict__ x, const float* __restrict__ hsrc,
    const h16* __restrict__ W1x, const h16* __restrict__ W1h) {
    extern __shared__ char smem[];
    h16* sp = (h16*)smem;
    const uint32_t sbase = smem_u32(smem);
    const int tid = threadIdx.x, wid = tid >> 5, lane = tid & 31;
    const int s = blockIdx.x, by = blockIdx.y;
    const float* A = s ? hsrc : x;
    const h16* B = s ? W1h : W1x;
    const int K = s ? H_SZ : IN_SZ;
    const int colOff = s * 64;
    const int NKT = K >> 5;
    const int nw = wid * 32;

    float acc[4][4][4];
#pragma unroll
    for (int a = 0; a < 4; ++a)
#pragma unroll
        for (int b = 0; b < 4; ++b)
#pragma unroll
            for (int q = 0; q < 4; ++q) acc[a][b][q] = 0.f;

    float4 aReg[2];
    auto fetchA = [&](int kt) {
#pragma unroll
        for (int i = 0; i < 2; ++i) {
            int id = tid + i * 256;
            int row = id >> 3, c4 = id & 7;
            aReg[i] = *(const float4*)(A + (size_t)(by * 64 + row) * K + kt * 32 + c4 * 4);
        }
    };
    auto stsA = [&](int st) {
        h16* d = sp + st * (G1_SSTR / 2);
#pragma unroll
        for (int i = 0; i < 2; ++i) {
            int id = tid + i * 256;
            int row = id >> 3, c4 = id & 7;
            uint32_t h01 = pack_h2(aReg[i].x, aReg[i].y);
            uint32_t h23 = pack_h2(aReg[i].z, aReg[i].w);
            *(uint2*)(d + row * 40 + c4 * 4) = make_uint2(h01, h23);
        }
    };
    auto cpB = [&](int kt, int st) {
        uint32_t sb = sbase + st * G1_SSTR;
#pragma unroll
        for (int i = 0; i < 4; ++i) {
            int id = tid + i * 256;
            int row = id >> 2, c = id & 3;
            size_t so = (size_t)row * K + kt * 32 + c * 8;
            uint32_t doff = (uint32_t)((2560 + row * 40 + c * 8) * 2);
            CP16(sb + doff, (const void*)(B + so));
        }
    };

    fetchA(0);
    stsA(0);
    cpB(0, 0);
    CPC();
    fetchA(1);

    for (int kt = 0; kt < NKT; ++kt) {
        int st = kt & 1;
        cpwait<0>();
        __syncthreads();
        if (kt + 1 < NKT) {
            stsA(st ^ 1);
            cpB(kt + 1, st ^ 1);
            CPC();
            if (kt + 2 < NKT) fetchA(kt + 2);
        }

        uint32_t sb = sbase + st * G1_SSTR;
#pragma unroll
        for (int ks = 0; ks < 2; ++ks) {
            uint32_t ah[4][4], bb[2][4];
            const int arow = (lane & 7) + ((lane >> 3) & 1) * 8;
            const int akc  = ks * 16 + (lane >> 4) * 8;
#pragma unroll
            for (int mf = 0; mf < 4; ++mf) {
                uint32_t ad = sb + (uint32_t)(((arow + mf * 16) * 40 + akc) * 2);
                ldsm4(ah[mf], ad);
            }
            const int bnr = nw + ((lane >> 4) << 3) + (lane & 7);
            const int bkc = ks * 16 + ((lane >> 3) & 1) * 8;
#pragma unroll
            for (int nh = 0; nh < 2; ++nh) {
                uint32_t bd = sb + (uint32_t)(((2560 + (bnr + nh * 16) * 40) + bkc) * 2);
                ldsm4(bb[nh], bd);
            }
#pragma unroll
            for (int mf = 0; mf < 4; ++mf)
#pragma unroll
                for (int nf = 0; nf < 4; ++nf) {
                    uint32_t b0 = bb[nf >> 1][(nf & 1) * 2], b1 = bb[nf >> 1][(nf & 1) * 2 + 1];
                    mma_f16(acc[mf][nf], ah[mf], b0, b1);
                }
        }
    }

#pragma unroll
    for (int mf = 0; mf < 4; ++mf)
#pragma unroll
        for (int nf = 0; nf < 4; ++nf) {
            int r0 = by * 64 + mf * 16 + (lane >> 2);
            int ncol = nw + nf * 8 + (lane & 3) * 2;
            int g = ncol >> 6;
            int tc = g * 128 + colOff + (ncol & 63);
            uint32_t hi, lo;
            split_pack(acc[mf][nf][0], acc[mf][nf][1], hi, lo);
            *(uint32_t*)&g_Th[(size_t)r0 * 512 + tc] = hi;
            *(uint32_t*)&g_Tl[(size_t)r0 * 512 + tc] = lo;
            split_pack(acc[mf][nf][2], acc[mf][nf][3], hi, lo);
            *(uint32_t*)&g_Th[(size_t)(r0 + 8) * 512 + tc] = hi;
            *(uint32_t*)&g_Tl[(size_t)(r0 + 8) * 512 + tc] = lo;
        }
}

// ---------------- GEMM2: m64 x n64 x 4g, 256 thr, 2 CTAs/SM, 2 stages, single-sync (R12) ----------------
#define G2_HDR  4096
#define G2_SSTR 36864
#define G2_SMEM (G2_HDR + 2 * G2_SSTR)

__global__ __launch_bounds__(256, 2) void gemm2_hmma(
    const float* __restrict__ x, const float* __restrict__ h, const float* __restrict__ c,
    const float* __restrict__ bias_f, const float* __restrict__ bias_i,
    const float* __restrict__ bias_c, const float* __restrict__ bias_o,
    float* __restrict__ out) {
    extern __shared__ char smem[];
    const uint32_t sbase = smem_u32(smem);
    const int tid = threadIdx.x, wid = tid >> 5, lane = tid & 31;
    const int bx = blockIdx.x, by = blockIdx.y;
    const int m0 = (wid & 3) * 16, n0w = (wid >> 2) * 32;

    float* ebias = (float*)smem;   // [4][64]
    float* ebu   = ebias + 256;
    float* eaw   = ebu + 256;
    {
        int g = tid >> 6, jl = tid & 63;
        int j = bx * 64 + jl;
        ebias[tid] = sel4(g, bias_f, bias_i, bias_c, bias_o)[j];
        ebu[tid]   = g_bu[g][j];
        eaw[tid]   = (j < IN_SZ) ? g_aw[g][j] : 0.f;
    }

    auto loadStage = [&](int kb, int st) {
        uint32_t sb = sbase + G2_HDR + st * G2_SSTR;
        const h16* Th = g_Th + (size_t)(by * 64) * 512 + kb * 16;
        const h16* Tl = g_Tl + (size_t)(by * 64) * 512 + kb * 16;
#pragma unroll
        for (int i = 0; i < 2; ++i) {
            int id = tid + i * 256;
            int g = id >> 7, rem = id & 127;
            int row = rem >> 1, cc = rem & 1;
            size_t so = (size_t)row * 512 + g * 128 + cc * 8;
            uint32_t doff = (uint32_t)(g * 3072 + row * 48 + cc * 16);
            CP16(sb + doff, (const void*)(Th + so));
            CP16(sb + 12288 + doff, (const void*)(Tl + so));
        }
#pragma unroll
        for (int i = 0; i < 2; ++i) {
            int id = tid + i * 256;
            int g = id >> 7, rem = id & 127;
            int n = rem >> 1, cc = rem & 1;
            size_t so = ((size_t)g * 1024 + bx * 64 + n) * 128 + kb * 16 + cc * 8;
            uint32_t doff = (uint32_t)(g * 3072 + n * 48 + cc * 16);
            CP16(sb + 24576 + doff, (const void*)(g_W2 + so));
        }
    };

    float acc[4][4][4];
#pragma unroll
    for (int a = 0; a < 4; ++a)
#pragma unroll
        for (int b = 0; b < 4; ++b)
#pragma unroll
            for (int q = 0; q < 4; ++q) acc[a][b][q] = 0.f;

    loadStage(0, 0);
    CPC();
    for (int kb = 0; kb < 8; ++kb) {
        int st = kb & 1;
        cpwait<0>();
        __syncthreads();
        if (kb < 7) {
            loadStage(kb + 1, st ^ 1);
            CPC();
        }

        uint32_t sb = sbase + G2_HDR + st * G2_SSTR;
        const int arow = m0 + (lane & 7) + ((lane >> 3) & 1) * 8;
        const int akc  = (lane >> 4) * 8;
        const int bnr = n0w + ((lane >> 4) << 3) + (lane & 7);
        const int bkc = ((lane >> 3) & 1) * 8;
#pragma unroll
        for (int g = 0; g < 4; ++g) {
            uint32_t ah[4], al[4], bb[2][4];
            uint32_t ad = sb + (uint32_t)(g * 3072 + arow * 48 + akc * 2);
            ldsm4(ah, ad);
            ldsm4(al, ad + 12288);
#pragma unroll
            for (int nh = 0; nh < 2; ++nh) {
                uint32_t bd = sb + (uint32_t)(24576 + g * 3072 + (bnr + nh * 16) * 48 + bkc * 2);
                ldsm4(bb[nh], bd);
            }
#pragma unroll
            for (int nf = 0; nf < 4; ++nf) {
                uint32_t b0 = bb[nf >> 1][(nf & 1) * 2], b1 = bb[nf >> 1][(nf & 1) * 2 + 1];
                mma_f16(acc[g][nf], ah, b0, b1);
                mma_f16(acc[g][nf], al, b0, b1);
            }
        }
    }

    // in-register LSTM epilogue
    const int r0 = m0 + (lane >> 2);
    const int jcb = n0w + (lane & 3) * 2;
    const bool hasx = (bx * 64 < IN_SZ);
    const size_t GS = (size_t)B_SZ * H_SZ;
#pragma unroll
    for (int nf = 0; nf < 4; ++nf) {
        int jl = jcb + nf * 8;
        int j = bx * 64 + jl;
#pragma unroll
        for (int rr = 0; rr < 2; ++rr) {
            int b = by * 64 + r0 + rr * 8;
            float2 h2 = *(const float2*)(h + (size_t)b * 1024 + j);
            float2 c2 = *(const float2*)(c + (size_t)b * 1024 + j);
            float2 x2 = hasx ? *(const float2*)(x + (size_t)b * IN_SZ + j) : make_float2(0.f, 0.f);
            float pr[4][2];
#pragma unroll
            for (int g = 0; g < 4; ++g) {
                pr[g][0] = acc[g][nf][rr * 2 + 0] + ebias[g * 64 + jl]     + h2.x * ebu[g * 64 + jl]     + x2.x * eaw[g * 64 + jl];
                pr[g][1] = acc[g][nf][rr * 2 + 1] + ebias[g * 64 + jl + 1] + h2.y * ebu[g * 64 + jl + 1] + x2.y * eaw[g * 64 + jl + 1];
            }
            float2 hn, cn;
            {
                float f = sigf(pr[0][0]), ii = sigf(pr[1][0]), gg = tanhfast(pr[2][0]), o = sigf(pr[3][0]);
                cn.x = f * c2.x + ii * gg;
                hn.x = o * tanhfast(cn.x);
            }
            {
                float f = sigf(pr[0][1]), ii = sigf(pr[1][1]), gg = tanhfast(pr[2][1]), o = sigf(pr[3][1]);
                cn.y = f * c2.y + ii * gg;
                hn.y = o * tanhfast(cn.y);
            }
            *(float2*)(out + (size_t)b * 1024 + j)      = hn;
            *(float2*)(out + GS + (size_t)b * 1024 + j) = cn;
        }
    }
}

// ---------------- launch ----------------
extern "C" void kernel_launch(void* const* d_in, const int* in_sizes, int n_in,
                              void* d_out, int out_size) {
    const float* x = (const float*)d_in[0];
    const float* h = (const float*)d_in[1];
    const float* c = (const float*)d_in[2];
    const float* Wu_f = (const float*)d_in[3];
    const float* Wu_i = (const float*)d_in[4];
    const float* Wu_c = (const float*)d_in[5];
    const float* Wu_o = (const float*)d_in[6];
    const float* Uu_f = (const float*)d_in[7];
    const float* Uu_i = (const float*)d_in[8];
    const float* Uu_c = (const float*)d_in[9];
    const float* Uu_o = (const float*)d_in[10];
    const float* Wf = (const float*)d_in[11];
    const float* Wi = (const float*)d_in[12];
    const float* Wc = (const float*)d_in[13];
    const float* Wo = (const float*)d_in[14];
    const float* Uf = (const float*)d_in[15];
    const float* Ui = (const float*)d_in[16];
    const float* Uc = (const float*)d_in[17];
    const float* Uo = (const float*)d_in[18];
    const float* bias_f = (const float*)d_in[19];
    const float* bias_i = (const float*)d_in[20];
    const float* bias_c = (const float*)d_in[21];
    const float* bias_o = (const float*)d_in[22];
    const float* W_dia = (const float*)d_in[23];
    const float* U_dia = (const float*)d_in[24];
    float* out = (float*)d_out;

    h16 *pW1x, *pW1h;
    cudaGetSymbolAddress((void**)&pW1x, g_W1x);
    cudaGetSymbolAddress((void**)&pW1h, g_W1h);

    cudaFuncSetAttribute(gemm1_hmma, cudaFuncAttributeMaxDynamicSharedMemorySize, G1_SMEM);
    cudaFuncSetAttribute(gemm2_hmma, cudaFuncAttributeMaxDynamicSharedMemorySize, G2_SMEM);

    prep_all<<<1072, 256>>>(Wu_f, Wu_i, Wu_c, Wu_o, Uu_f, Uu_i, Uu_c, Uu_o,
                            Wf, Wi, Wc, Wo, Uf, Ui, Uc, Uo, W_dia, U_dia);

    gemm1_hmma<<<dim3(2, B_SZ / 64), 256, G1_SMEM>>>(x, h, pW1x, pW1h);

    gemm2_hmma<<<dim3(H_SZ / 64, B_SZ / 64), 256, G2_SMEM>>>(
        x, h, c, bias_f, bias_i, bias_c, bias_o, out);
}

// round 15
// speedup vs baseline: 1.2891x; 1.2176x over previous
#include <cuda_runtime.h>
#include <cuda_fp16.h>
#include <cstdint>

typedef __half h16;
#define B_SZ  16384
#define IN_SZ 768
#define H_SZ  1024

// ---------------- scratch ----------------
__device__ h16 g_Th[(size_t)B_SZ * 512];     // T in single fp16 (lo term dropped)
__device__ h16 g_W1x[256 * IN_SZ];
__device__ h16 g_W1h[256 * H_SZ];
__device__ h16 g_W2[(size_t)4 * H_SZ * 128];
__device__ float g_aw[4][IN_SZ];
__device__ float g_bu[4][H_SZ];

// ---------------- helpers ----------------
__device__ __forceinline__ uint32_t smem_u32(const void* p) {
    uint32_t a;
    asm("{ .reg .u64 t; cvta.to.shared.u64 t, %1; cvt.u32.u64 %0, t; }" : "=r"(a) : "l"(p));
    return a;
}
__device__ __forceinline__ void ldsm4(uint32_t (&r)[4], uint32_t a) {
    asm volatile("ldmatrix.sync.aligned.m8n8.x4.shared.b16 {%0,%1,%2,%3}, [%4];"
                 : "=r"(r[0]), "=r"(r[1]), "=r"(r[2]), "=r"(r[3]) : "r"(a));
}
__device__ __forceinline__ void mma_f16(float (&c)[4], const uint32_t (&a)[4],
                                        uint32_t b0, uint32_t b1) {
    asm volatile(
        "mma.sync.aligned.m16n8k16.row.col.f32.f16.f16.f32 "
        "{%0,%1,%2,%3},{%4,%5,%6,%7},{%8,%9},{%0,%1,%2,%3};"
        : "+f"(c[0]), "+f"(c[1]), "+f"(c[2]), "+f"(c[3])
        : "r"(a[0]), "r"(a[1]), "r"(a[2]), "r"(a[3]), "r"(b0), "r"(b1));
}
#define CP16(s, g) asm volatile("cp.async.cg.shared.global [%0], [%1], 16;" :: "r"(s), "l"(g))
#define CPC()      asm volatile("cp.async.commit_group;")
template <int N> __device__ __forceinline__ void cpwait() {
    asm volatile("cp.async.wait_group %0;" :: "n"(N));
}
__device__ __forceinline__ uint32_t pack_h2(float a, float b) {
    h16 ha = __float2half_rn(a), hb = __float2half_rn(b);
    return (uint32_t)__half_as_ushort(ha) | ((uint32_t)__half_as_ushort(hb) << 16);
}
__device__ __forceinline__ const float* sel4(int g, const float* a, const float* b,
                                             const float* c, const float* d) {
    return g == 0 ? a : g == 1 ? b : g == 2 ? c : d;
}
__device__ __forceinline__ float sigf(float z) {
    z = fminf(fmaxf(z, -30.f), 30.f);
    return 1.f / (1.f + __expf(-z));
}
__device__ __forceinline__ float tanhfast(float z) {
    z = fminf(fmaxf(z, -15.f), 15.f);
    float e = __expf(-2.f * z);
    return (1.f - e) / (1.f + e);
}

// ---------------- fused prep (R14, unchanged) ----------------
__global__ void prep_all(const float* __restrict__ Wu_f, const float* __restrict__ Wu_i,
                         const float* __restrict__ Wu_c, const float* __restrict__ Wu_o,
                         const float* __restrict__ Uu_f, const float* __restrict__ Uu_i,
                         const float* __restrict__ Uu_c, const float* __restrict__ Uu_o,
                         const float* __restrict__ Wf, const float* __restrict__ Wi,
                         const float* __restrict__ Wc, const float* __restrict__ Wo,
                         const float* __restrict__ Uf, const float* __restrict__ Ui,
                         const float* __restrict__ Uc, const float* __restrict__ Uo,
                         const float* __restrict__ W_dia, const float* __restrict__ U_dia) {
    __shared__ __align__(16) float buf[4608];
    const int b = blockIdx.x, tid = threadIdx.x;
    const int tx = tid & 31, ty = tid >> 5;

    if (b < 448) {
        const bool isx = (b < 192);
        const int bi = isx ? b : b - 192;
        const int K = isx ? IN_SZ : H_SZ;
        const int nkt = K >> 5;
        const int kt = bi % nkt, nt = bi / nkt;
        const int k0 = kt * 32;
        const int g = nt >> 1, r0 = (nt & 1) * 32;
        const float* F = isx ? sel4(g, Wu_f, Wu_i, Wu_c, Wu_o)
                             : sel4(g, Uu_f, Uu_i, Uu_c, Uu_o);
        h16* D = isx ? g_W1x : g_W1h;
        float (*t)[33] = (float(*)[33])buf;
#pragma unroll
        for (int i = 0; i < 4; ++i)
            t[ty + i * 8][tx] = F[(size_t)(k0 + ty + i * 8) * 64 + r0 + tx];
        __syncthreads();
#pragma unroll
        for (int i = 0; i < 4; ++i) {
            int row = ty + i * 8;
            int n = nt * 32 + row, k = k0 + tx;
            D[(size_t)n * K + k] = __float2half_rn(t[tx][row]);
        }
    } else if (b < 960) {
        const int i = b - 448;
        const int k0 = (i & 3) * 32, n0 = ((i >> 2) & 31) * 32, g = i >> 7;
        const float* S = (k0 < 64) ? sel4(g, Wf, Wi, Wc, Wo) : sel4(g, Uf, Ui, Uc, Uo);
        const int kr0 = (k0 < 64) ? k0 : k0 - 64;
        float (*t)[33] = (float(*)[33])buf;
#pragma unroll
        for (int q = 0; q < 4; ++q)
            t[ty + q * 8][tx] = S[(size_t)(kr0 + ty + q * 8) * H_SZ + n0 + tx];
        __syncthreads();
#pragma unroll
        for (int q = 0; q < 4; ++q) {
            int row = ty + q * 8;
            int n = n0 + row, k = k0 + tx;
            g_W2[((size_t)g * H_SZ + n) * 128 + k] = __float2half_rn(t[tx][row]);
        }
    } else {
        const int bb = b - 960;
        const bool uside = (bb < 64);
        int g, j0;
        const float *Fu, *Fv;
        if (uside) {
            g = bb >> 4; j0 = (bb & 15) * 64;
            Fu = sel4(g, Uu_f, Uu_i, Uu_c, Uu_o);
            Fv = sel4(g, Uf, Ui, Uc, Uo);
        } else {
            int t2 = bb - 64;
            g = t2 / 12; j0 = (t2 % 12) * 64;
            Fu = sel4(g, Wu_f, Wu_i, Wu_c, Wu_o);
            Fv = sel4(g, Wf, Wi, Wc, Wo);
        }
        float (*fu)[68] = (float(*)[68])buf;
        float (*red)[64] = (float(*)[64])(buf + 4352);
#pragma unroll
        for (int i = 0; i < 4; ++i) {
            int id = tid + i * 256;
            int jj = id >> 4, rb = (id & 15) * 4;
            *(float4*)&fu[jj][rb] = *(const float4*)(Fu + (size_t)(j0 + jj) * 64 + rb);
        }
        __syncthreads();
        int jl = tid & 63, rq = tid >> 6;
        float s = 0.f;
#pragma unroll
        for (int i = 0; i < 16; ++i) {
            int r = rq * 16 + i;
            s += fu[jl][r] * Fv[(size_t)r * H_SZ + j0 + jl];
        }
        red[rq][jl] = s;
        __syncthreads();
        if (rq == 0) {
            float tot = red[0][jl] + red[1][jl] + red[2][jl] + red[3][jl];
            int j = j0 + jl;
            if (uside) g_bu[g][j] = U_dia[j] - tot;
            else       g_aw[g][j] = W_dia[j] - tot;
        }
    }
}

// ---------------- GEMM1: m64 x n256, 256 thr, 2 CTAs/SM, 2 stages, single-sync ----------------
#define G1_SSTR 25600
#define G1_SMEM (2 * G1_SSTR)

__global__ __launch_bounds__(256, 2) void gemm1_hmma(
    const float* __restrict__ x, const float* __restrict__ hsrc,
    const h16* __restrict__ W1x, const h16* __restrict__ W1h) {
    extern __shared__ char smem[];
    h16* sp = (h16*)smem;
    const uint32_t sbase = smem_u32(smem);
    const int tid = threadIdx.x, wid = tid >> 5, lane = tid & 31;
    const int s = blockIdx.x, by = blockIdx.y;
    const float* A = s ? hsrc : x;
    const h16* B = s ? W1h : W1x;
    const int K = s ? H_SZ : IN_SZ;
    const int colOff = s * 64;
    const int NKT = K >> 5;
    const int nw = wid * 32;

    float acc[4][4][4];
#pragma unroll
    for (int a = 0; a < 4; ++a)
#pragma unroll
        for (int b = 0; b < 4; ++b)
#pragma unroll
            for (int q = 0; q < 4; ++q) acc[a][b][q] = 0.f;

    float4 aReg[2];
    auto fetchA = [&](int kt) {
#pragma unroll
        for (int i = 0; i < 2; ++i) {
            int id = tid + i * 256;
            int row = id >> 3, c4 = id & 7;
            aReg[i] = *(const float4*)(A + (size_t)(by * 64 + row) * K + kt * 32 + c4 * 4);
        }
    };
    auto stsA = [&](int st) {
        h16* d = sp + st * (G1_SSTR / 2);
#pragma unroll
        for (int i = 0; i < 2; ++i) {
            int id = tid + i * 256;
            int row = id >> 3, c4 = id & 7;
            uint32_t h01 = pack_h2(aReg[i].x, aReg[i].y);
            uint32_t h23 = pack_h2(aReg[i].z, aReg[i].w);
            *(uint2*)(d + row * 40 + c4 * 4) = make_uint2(h01, h23);
        }
    };
    auto cpB = [&](int kt, int st) {
        uint32_t sb = sbase + st * G1_SSTR;
#pragma unroll
        for (int i = 0; i < 4; ++i) {
            int id = tid + i * 256;
            int row = id >> 2, c = id & 3;
            size_t so = (size_t)row * K + kt * 32 + c * 8;
            uint32_t doff = (uint32_t)((2560 + row * 40 + c * 8) * 2);
            CP16(sb + doff, (const void*)(B + so));
        }
    };

    fetchA(0);
    stsA(0);
    cpB(0, 0);
    CPC();
    fetchA(1);

    for (int kt = 0; kt < NKT; ++kt) {
        int st = kt & 1;
        cpwait<0>();
        __syncthreads();
        if (kt + 1 < NKT) {
            stsA(st ^ 1);
            cpB(kt + 1, st ^ 1);
            CPC();
            if (kt + 2 < NKT) fetchA(kt + 2);
        }

        uint32_t sb = sbase + st * G1_SSTR;
#pragma unroll
        for (int ks = 0; ks < 2; ++ks) {
            uint32_t ah[4][4], bb[2][4];
            const int arow = (lane & 7) + ((lane >> 3) & 1) * 8;
            const int akc  = ks * 16 + (lane >> 4) * 8;
#pragma unroll
            for (int mf = 0; mf < 4; ++mf) {
                uint32_t ad = sb + (uint32_t)(((arow + mf * 16) * 40 + akc) * 2);
                ldsm4(ah[mf], ad);
            }
            const int bnr = nw + ((lane >> 4) << 3) + (lane & 7);
            const int bkc = ks * 16 + ((lane >> 3) & 1) * 8;
#pragma unroll
            for (int nh = 0; nh < 2; ++nh) {
                uint32_t bd = sb + (uint32_t)(((2560 + (bnr + nh * 16) * 40) + bkc) * 2);
                ldsm4(bb[nh], bd);
            }
#pragma unroll
            for (int mf = 0; mf < 4; ++mf)
#pragma unroll
                for (int nf = 0; nf < 4; ++nf) {
                    uint32_t b0 = bb[nf >> 1][(nf & 1) * 2], b1 = bb[nf >> 1][(nf & 1) * 2 + 1];
                    mma_f16(acc[mf][nf], ah[mf], b0, b1);
                }
        }
    }

    // epilogue: single fp16 T (lo term dropped)
#pragma unroll
    for (int mf = 0; mf < 4; ++mf)
#pragma unroll
        for (int nf = 0; nf < 4; ++nf) {
            int r0 = by * 64 + mf * 16 + (lane >> 2);
            int ncol = nw + nf * 8 + (lane & 3) * 2;
            int g = ncol >> 6;
            int tc = g * 128 + colOff + (ncol & 63);
            *(uint32_t*)&g_Th[(size_t)r0 * 512 + tc] = pack_h2(acc[mf][nf][0], acc[mf][nf][1]);
            *(uint32_t*)&g_Th[(size_t)(r0 + 8) * 512 + tc] = pack_h2(acc[mf][nf][2], acc[mf][nf][3]);
        }
}

// ---------------- GEMM2: m64 x n64 x 4g, 256 thr, 2 CTAs/SM, single T term ----------------
// Stage: A 0..12287 (4g*64*48B), B 12288..24575 (4g*64*48B); stride 24576.
#define G2_HDR  4096
#define G2_SSTR 24576
#define G2_SMEM (G2_HDR + 2 * G2_SSTR)

__global__ __launch_bounds__(256, 2) void gemm2_hmma(
    const float* __restrict__ x, const float* __restrict__ h, const float* __restrict__ c,
    const float* __restrict__ bias_f, const float* __restrict__ bias_i,
    const float* __restrict__ bias_c, const float* __restrict__ bias_o,
    float* __restrict__ out) {
    extern __shared__ char smem[];
    const uint32_t sbase = smem_u32(smem);
    const int tid = threadIdx.x, wid = tid >> 5, lane = tid & 31;
    const int bx = blockIdx.x, by = blockIdx.y;
    const int m0 = (wid & 3) * 16, n0w = (wid >> 2) * 32;

    float* ebias = (float*)smem;   // [4][64]
    float* ebu   = ebias + 256;
    float* eaw   = ebu + 256;
    {
        int g = tid >> 6, jl = tid & 63;
        int j = bx * 64 + jl;
        ebias[tid] = sel4(g, bias_f, bias_i, bias_c, bias_o)[j];
        ebu[tid]   = g_bu[g][j];
        eaw[tid]   = (j < IN_SZ) ? g_aw[g][j] : 0.f;
    }

    auto loadStage = [&](int kb, int st) {
        uint32_t sb = sbase + G2_HDR + st * G2_SSTR;
        const h16* Th = g_Th + (size_t)(by * 64) * 512 + kb * 16;
#pragma unroll
        for (int i = 0; i < 2; ++i) {
            int id = tid + i * 256;
            int g = id >> 7, rem = id & 127;
            int row = rem >> 1, cc = rem & 1;
            size_t so = (size_t)row * 512 + g * 128 + cc * 8;
            uint32_t doff = (uint32_t)(g * 3072 + row * 48 + cc * 16);
            CP16(sb + doff, (const void*)(Th + so));
        }
#pragma unroll
        for (int i = 0; i < 2; ++i) {
            int id = tid + i * 256;
            int g = id >> 7, rem = id & 127;
            int n = rem >> 1, cc = rem & 1;
            size_t so = ((size_t)g * 1024 + bx * 64 + n) * 128 + kb * 16 + cc * 8;
            uint32_t doff = (uint32_t)(12288 + g * 3072 + n * 48 + cc * 16);
            CP16(sb + doff, (const void*)(g_W2 + so));
        }
    };

    float acc[4][4][4];
#pragma unroll
    for (int a = 0; a < 4; ++a)
#pragma unroll
        for (int b = 0; b < 4; ++b)
#pragma unroll
            for (int q = 0; q < 4; ++q) acc[a][b][q] = 0.f;

    loadStage(0, 0);
    CPC();
    for (int kb = 0; kb < 8; ++kb) {
        int st = kb & 1;
        cpwait<0>();
        __syncthreads();
        if (kb < 7) {
            loadStage(kb + 1, st ^ 1);
            CPC();
        }

        uint32_t sb = sbase + G2_HDR + st * G2_SSTR;
        const int arow = m0 + (lane & 7) + ((lane >> 3) & 1) * 8;
        const int akc  = (lane >> 4) * 8;
        const int bnr = n0w + ((lane >> 4) << 3) + (lane & 7);
        const int bkc = ((lane >> 3) & 1) * 8;
#pragma unroll
        for (int g = 0; g < 4; ++g) {
            uint32_t ah[4], bb[2][4];
            uint32_t ad = sb + (uint32_t)(g * 3072 + arow * 48 + akc * 2);
            ldsm4(ah, ad);
#pragma unroll
            for (int nh = 0; nh < 2; ++nh) {
                uint32_t bd = sb + (uint32_t)(12288 + g * 3072 + (bnr + nh * 16) * 48 + bkc * 2);
                ldsm4(bb[nh], bd);
            }
#pragma unroll
            for (int nf = 0; nf < 4; ++nf) {
                uint32_t b0 = bb[nf >> 1][(nf & 1) * 2], b1 = bb[nf >> 1][(nf & 1) * 2 + 1];
                mma_f16(acc[g][nf], ah, b0, b1);
            }
        }
    }

    // in-register LSTM epilogue
    const int r0 = m0 + (lane >> 2);
    const int jcb = n0w + (lane & 3) * 2;
    const bool hasx = (bx * 64 < IN_SZ);
    const size_t GS = (size_t)B_SZ * H_SZ;
#pragma unroll
    for (int nf = 0; nf < 4; ++nf) {
        int jl = jcb + nf * 8;
        int j = bx * 64 + jl;
#pragma unroll
        for (int rr = 0; rr < 2; ++rr) {
            int b = by * 64 + r0 + rr * 8;
            float2 h2 = *(const float2*)(h + (size_t)b * 1024 + j);
            float2 c2 = *(const float2*)(c + (size_t)b * 1024 + j);
            float2 x2 = hasx ? *(const float2*)(x + (size_t)b * IN_SZ + j) : make_float2(0.f, 0.f);
            float pr[4][2];
#pragma unroll
            for (int g = 0; g < 4; ++g) {
                pr[g][0] = acc[g][nf][rr * 2 + 0] + ebias[g * 64 + jl]     + h2.x * ebu[g * 64 + jl]     + x2.x * eaw[g * 64 + jl];
                pr[g][1] = acc[g][nf][rr * 2 + 1] + ebias[g * 64 + jl + 1] + h2.y * ebu[g * 64 + jl + 1] + x2.y * eaw[g * 64 + jl + 1];
            }
            float2 hn, cn;
            {
                float f = sigf(pr[0][0]), ii = sigf(pr[1][0]), gg = tanhfast(pr[2][0]), o = sigf(pr[3][0]);
                cn.x = f * c2.x + ii * gg;
                hn.x = o * tanhfast(cn.x);
            }
            {
                float f = sigf(pr[0][1]), ii = sigf(pr[1][1]), gg = tanhfast(pr[2][1]), o = sigf(pr[3][1]);
                cn.y = f * c2.y + ii * gg;
                hn.y = o * tanhfast(cn.y);
            }
            *(float2*)(out + (size_t)b * 1024 + j)      = hn;
            *(float2*)(out + GS + (size_t)b * 1024 + j) = cn;
        }
    }
}

// ---------------- launch ----------------
extern "C" void kernel_launch(void* const* d_in, const int* in_sizes, int n_in,
                              void* d_out, int out_size) {
    const float* x = (const float*)d_in[0];
    const float* h = (const float*)d_in[1];
    const float* c = (const float*)d_in[2];
    const float* Wu_f = (const float*)d_in[3];
    const float* Wu_i = (const float*)d_in[4];
    const float* Wu_c = (const float*)d_in[5];
    const float* Wu_o = (const float*)d_in[6];
    const float* Uu_f = (const float*)d_in[7];
    const float* Uu_i = (const float*)d_in[8];
    const float* Uu_c = (const float*)d_in[9];
    const float* Uu_o = (const float*)d_in[10];
    const float* Wf = (const float*)d_in[11];
    const float* Wi = (const float*)d_in[12];
    const float* Wc = (const float*)d_in[13];
    const float* Wo = (const float*)d_in[14];
    const float* Uf = (const float*)d_in[15];
    const float* Ui = (const float*)d_in[16];
    const float* Uc = (const float*)d_in[17];
    const float* Uo = (const float*)d_in[18];
    const float* bias_f = (const float*)d_in[19];
    const float* bias_i = (const float*)d_in[20];
    const float* bias_c = (const float*)d_in[21];
    const float* bias_o = (const float*)d_in[22];
    const float* W_dia = (const float*)d_in[23];
    const float* U_dia = (const float*)d_in[24];
    float* out = (float*)d_out;

    h16 *pW1x, *pW1h;
    cudaGetSymbolAddress((void**)&pW1x, g_W1x);
    cudaGetSymbolAddress((void**)&pW1h, g_W1h);

    cudaFuncSetAttribute(gemm1_hmma, cudaFuncAttributeMaxDynamicSharedMemorySize, G1_SMEM);
    cudaFuncSetAttribute(gemm2_hmma, cudaFuncAttributeMaxDynamicSharedMemorySize, G2_SMEM);

    prep_all<<<1072, 256>>>(Wu_f, Wu_i, Wu_c, Wu_o, Uu_f, Uu_i, Uu_c, Uu_o,
                            Wf, Wi, Wc, Wo, Uf, Ui, Uc, Uo, W_dia, U_dia);

    gemm1_hmma<<<dim3(2, B_SZ / 64), 256, G1_SMEM>>>(x, h, pW1x, pW1h);

    gemm2_hmma<<<dim3(H_SZ / 64, B_SZ / 64), 256, G2_SMEM>>>(
        x, h, c, bias_f, bias_i, bias_c, bias_o, out);
}

// round 16
// speedup vs baseline: 1.4243x; 1.1049x over previous
#include <cuda_runtime.h>
#include <cuda_fp16.h>
#include <cstdint>

typedef __half h16;
#define B_SZ  16384
#define IN_SZ 768
#define H_SZ  1024

// ---------------- scratch ----------------
__device__ h16 g_Th[(size_t)B_SZ * 512];
__device__ h16 g_W1x[256 * IN_SZ];
__device__ h16 g_W1h[256 * H_SZ];
__device__ h16 g_W2[(size_t)4 * H_SZ * 128];
__device__ float g_aw[4][IN_SZ];
__device__ float g_bu[4][H_SZ];

// ---------------- helpers ----------------
__device__ __forceinline__ uint32_t smem_u32(const void* p) {
    uint32_t a;
    asm("{ .reg .u64 t; cvta.to.shared.u64 t, %1; cvt.u32.u64 %0, t; }" : "=r"(a) : "l"(p));
    return a;
}
__device__ __forceinline__ void ldsm4(uint32_t (&r)[4], uint32_t a) {
    asm volatile("ldmatrix.sync.aligned.m8n8.x4.shared.b16 {%0,%1,%2,%3}, [%4];"
                 : "=r"(r[0]), "=r"(r[1]), "=r"(r[2]), "=r"(r[3]) : "r"(a));
}
__device__ __forceinline__ void mma_f16(float (&c)[4], const uint32_t (&a)[4],
                                        uint32_t b0, uint32_t b1) {
    asm volatile(
        "mma.sync.aligned.m16n8k16.row.col.f32.f16.f16.f32 "
        "{%0,%1,%2,%3},{%4,%5,%6,%7},{%8,%9},{%0,%1,%2,%3};"
        : "+f"(c[0]), "+f"(c[1]), "+f"(c[2]), "+f"(c[3])
        : "r"(a[0]), "r"(a[1]), "r"(a[2]), "r"(a[3]), "r"(b0), "r"(b1));
}
#define CP16(s, g) asm volatile("cp.async.cg.shared.global [%0], [%1], 16;" :: "r"(s), "l"(g))
#define CPC()      asm volatile("cp.async.commit_group;")
template <int N> __device__ __forceinline__ void cpwait() {
    asm volatile("cp.async.wait_group %0;" :: "n"(N));
}
__device__ __forceinline__ uint32_t pack_h2(float a, float b) {
    h16 ha = __float2half_rn(a), hb = __float2half_rn(b);
    return (uint32_t)__half_as_ushort(ha) | ((uint32_t)__half_as_ushort(hb) << 16);
}
__device__ __forceinline__ const float* sel4(int g, const float* a, const float* b,
                                             const float* c, const float* d) {
    return g == 0 ? a : g == 1 ? b : g == 2 ? c : d;
}
__device__ __forceinline__ float sigf(float z) {
    z = fminf(fmaxf(z, -30.f), 30.f);
    return 1.f / (1.f + __expf(-z));
}
__device__ __forceinline__ float tanhfast(float z) {
    z = fminf(fmaxf(z, -15.f), 15.f);
    float e = __expf(-2.f * z);
    return (1.f - e) / (1.f + e);
}

// ---------------- fused prep (unchanged) ----------------
__global__ void prep_all(const float* __restrict__ Wu_f, const float* __restrict__ Wu_i,
                         const float* __restrict__ Wu_c, const float* __restrict__ Wu_o,
                         const float* __restrict__ Uu_f, const float* __restrict__ Uu_i,
                         const float* __restrict__ Uu_c, const float* __restrict__ Uu_o,
                         const float* __restrict__ Wf, const float* __restrict__ Wi,
                         const float* __restrict__ Wc, const float* __restrict__ Wo,
                         const float* __restrict__ Uf, const float* __restrict__ Ui,
                         const float* __restrict__ Uc, const float* __restrict__ Uo,
                         const float* __restrict__ W_dia, const float* __restrict__ U_dia) {
    __shared__ __align__(16) float buf[4608];
    const int b = blockIdx.x, tid = threadIdx.x;
    const int tx = tid & 31, ty = tid >> 5;

    if (b < 448) {
        const bool isx = (b < 192);
        const int bi = isx ? b : b - 192;
        const int K = isx ? IN_SZ : H_SZ;
        const int nkt = K >> 5;
        const int kt = bi % nkt, nt = bi / nkt;
        const int k0 = kt * 32;
        const int g = nt >> 1, r0 = (nt & 1) * 32;
        const float* F = isx ? sel4(g, Wu_f, Wu_i, Wu_c, Wu_o)
                             : sel4(g, Uu_f, Uu_i, Uu_c, Uu_o);
        h16* D = isx ? g_W1x : g_W1h;
        float (*t)[33] = (float(*)[33])buf;
#pragma unroll
        for (int i = 0; i < 4; ++i)
            t[ty + i * 8][tx] = F[(size_t)(k0 + ty + i * 8) * 64 + r0 + tx];
        __syncthreads();
#pragma unroll
        for (int i = 0; i < 4; ++i) {
            int row = ty + i * 8;
            int n = nt * 32 + row, k = k0 + tx;
            D[(size_t)n * K + k] = __float2half_rn(t[tx][row]);
        }
    } else if (b < 960) {
        const int i = b - 448;
        const int k0 = (i & 3) * 32, n0 = ((i >> 2) & 31) * 32, g = i >> 7;
        const float* S = (k0 < 64) ? sel4(g, Wf, Wi, Wc, Wo) : sel4(g, Uf, Ui, Uc, Uo);
        const int kr0 = (k0 < 64) ? k0 : k0 - 64;
        float (*t)[33] = (float(*)[33])buf;
#pragma unroll
        for (int q = 0; q < 4; ++q)
            t[ty + q * 8][tx] = S[(size_t)(kr0 + ty + q * 8) * H_SZ + n0 + tx];
        __syncthreads();
#pragma unroll
        for (int q = 0; q < 4; ++q) {
            int row = ty + q * 8;
            int n = n0 + row, k = k0 + tx;
            g_W2[((size_t)g * H_SZ + n) * 128 + k] = __float2half_rn(t[tx][row]);
        }
    } else {
        const int bb = b - 960;
        const bool uside = (bb < 64);
        int g, j0;
        const float *Fu, *Fv;
        if (uside) {
            g = bb >> 4; j0 = (bb & 15) * 64;
            Fu = sel4(g, Uu_f, Uu_i, Uu_c, Uu_o);
            Fv = sel4(g, Uf, Ui, Uc, Uo);
        } else {
            int t2 = bb - 64;
            g = t2 / 12; j0 = (t2 % 12) * 64;
            Fu = sel4(g, Wu_f, Wu_i, Wu_c, Wu_o);
            Fv = sel4(g, Wf, Wi, Wc, Wo);
        }
        float (*fu)[68] = (float(*)[68])buf;
        float (*red)[64] = (float(*)[64])(buf + 4352);
#pragma unroll
        for (int i = 0; i < 4; ++i) {
            int id = tid + i * 256;
            int jj = id >> 4, rb = (id & 15) * 4;
            *(float4*)&fu[jj][rb] = *(const float4*)(Fu + (size_t)(j0 + jj) * 64 + rb);
        }
        __syncthreads();
        int jl = tid & 63, rq = tid >> 6;
        float s = 0.f;
#pragma unroll
        for (int i = 0; i < 16; ++i) {
            int r = rq * 16 + i;
            s += fu[jl][r] * Fv[(size_t)r * H_SZ + j0 + jl];
        }
        red[rq][jl] = s;
        __syncthreads();
        if (rq == 0) {
            float tot = red[0][jl] + red[1][jl] + red[2][jl] + red[3][jl];
            int j = j0 + jl;
            if (uside) g_bu[g][j] = U_dia[j] - tot;
            else       g_aw[g][j] = W_dia[j] - tot;
        }
    }
}

// ---------------- GEMM1: m64 x n256, BK=64, 256 thr, 2 CTAs/SM ----------------
// Stage (halves): A 0..4607 (64 rows x 72), B 4608..23039 (256 rows x 72). Stage 46080 B.
#define G1_SSTR 46080
#define G1_SMEM (2 * G1_SSTR)

__global__ __launch_bounds__(256, 2) void gemm1_hmma(
    const float* __restrict__ x, const float* __restrict__ hsrc,
    const h16* __restrict__ W1x, const h16* __restrict__ W1h) {
    extern __shared__ char smem[];
    h16* sp = (h16*)smem;
    const uint32_t sbase = smem_u32(smem);
    const int tid = threadIdx.x, wid = tid >> 5, lane = tid & 31;
    const int s = blockIdx.x, by = blockIdx.y;
    const float* A = s ? hsrc : x;
    const h16* B = s ? W1h : W1x;
    const int K = s ? H_SZ : IN_SZ;
    const int colOff = s * 64;
    const int NKT = K >> 6;      // 12 or 16
    const int nw = wid * 32;

    float acc[4][4][4];
#pragma unroll
    for (int a = 0; a < 4; ++a)
#pragma unroll
        for (int b = 0; b < 4; ++b)
#pragma unroll
            for (int q = 0; q < 4; ++q) acc[a][b][q] = 0.f;

    float4 aReg[4];
    auto fetchA = [&](int kt) {
#pragma unroll
        for (int i = 0; i < 4; ++i) {
            int id = tid + i * 256;              // 1024 float4 = 64 rows x 16
            int row = id >> 4, c4 = id & 15;
            aReg[i] = *(const float4*)(A + (size_t)(by * 64 + row) * K + kt * 64 + c4 * 4);
        }
    };
    auto stsA = [&](int st) {
        h16* d = sp + st * (G1_SSTR / 2);
#pragma unroll
        for (int i = 0; i < 4; ++i) {
            int id = tid + i * 256;
            int row = id >> 4, c4 = id & 15;
            uint32_t h01 = pack_h2(aReg[i].x, aReg[i].y);
            uint32_t h23 = pack_h2(aReg[i].z, aReg[i].w);
            *(uint2*)(d + row * 72 + c4 * 4) = make_uint2(h01, h23);
        }
    };
    auto cpB = [&](int kt, int st) {
        uint32_t sb = sbase + st * G1_SSTR;
#pragma unroll
        for (int i = 0; i < 8; ++i) {
            int id = tid + i * 256;              // 2048 chunks = 256 rows x 8
            int row = id >> 3, c = id & 7;
            size_t so = (size_t)row * K + kt * 64 + c * 8;
            uint32_t doff = (uint32_t)((4608 + row * 72 + c * 8) * 2);
            CP16(sb + doff, (const void*)(B + so));
        }
    };

    fetchA(0);
    stsA(0);
    cpB(0, 0);
    CPC();
    fetchA(1);

    for (int kt = 0; kt < NKT; ++kt) {
        int st = kt & 1;
        cpwait<0>();
        __syncthreads();
        if (kt + 1 < NKT) {
            stsA(st ^ 1);
            cpB(kt + 1, st ^ 1);
            CPC();
            if (kt + 2 < NKT) fetchA(kt + 2);
        }

        uint32_t sb = sbase + st * G1_SSTR;
#pragma unroll
        for (int ks = 0; ks < 4; ++ks) {
            uint32_t ah[4][4], bb[2][4];
            const int arow = (lane & 7) + ((lane >> 3) & 1) * 8;
            const int akc  = ks * 16 + (lane >> 4) * 8;
#pragma unroll
            for (int mf = 0; mf < 4; ++mf) {
                uint32_t ad = sb + (uint32_t)(((arow + mf * 16) * 72 + akc) * 2);
                ldsm4(ah[mf], ad);
            }
            const int bnr = nw + ((lane >> 4) << 3) + (lane & 7);
            const int bkc = ks * 16 + ((lane >> 3) & 1) * 8;
#pragma unroll
            for (int nh = 0; nh < 2; ++nh) {
                uint32_t bd = sb + (uint32_t)(((4608 + (bnr + nh * 16) * 72) + bkc) * 2);
                ldsm4(bb[nh], bd);
            }
#pragma unroll
            for (int mf = 0; mf < 4; ++mf)
#pragma unroll
                for (int nf = 0; nf < 4; ++nf) {
                    uint32_t b0 = bb[nf >> 1][(nf & 1) * 2], b1 = bb[nf >> 1][(nf & 1) * 2 + 1];
                    mma_f16(acc[mf][nf], ah[mf], b0, b1);
                }
        }
    }

#pragma unroll
    for (int mf = 0; mf < 4; ++mf)
#pragma unroll
        for (int nf = 0; nf < 4; ++nf) {
            int r0 = by * 64 + mf * 16 + (lane >> 2);
            int ncol = nw + nf * 8 + (lane & 3) * 2;
            int g = ncol >> 6;
            int tc = g * 128 + colOff + (ncol & 63);
            *(uint32_t*)&g_Th[(size_t)r0 * 512 + tc] = pack_h2(acc[mf][nf][0], acc[mf][nf][1]);
            *(uint32_t*)&g_Th[(size_t)(r0 + 8) * 512 + tc] = pack_h2(acc[mf][nf][2], acc[mf][nf][3]);
        }
}

// ---------------- GEMM2: m64 x n64 x 4g, k-chunk 32 (4 iters), 2 CTAs/SM ----------------
// Stage (halves): A 0..10239 (4g x 64 rows x 40), B 10240..20479. Stage 40960 B.
#define G2_HDR  4096
#define G2_SSTR 40960
#define G2_SMEM (G2_HDR + 2 * G2_SSTR)

__global__ __launch_bounds__(256, 2) void gemm2_hmma(
    const float* __restrict__ x, const float* __restrict__ h, const float* __restrict__ c,
    const float* __restrict__ bias_f, const float* __restrict__ bias_i,
    const float* __restrict__ bias_c, const float* __restrict__ bias_o,
    float* __restrict__ out) {
    extern __shared__ char smem[];
    const uint32_t sbase = smem_u32(smem);
    const int tid = threadIdx.x, wid = tid >> 5, lane = tid & 31;
    const int bx = blockIdx.x, by = blockIdx.y;
    const int m0 = (wid & 3) * 16, n0w = (wid >> 2) * 32;

    float* ebias = (float*)smem;   // [4][64]
    float* ebu   = ebias + 256;
    float* eaw   = ebu + 256;
    {
        int g = tid >> 6, jl = tid & 63;
        int j = bx * 64 + jl;
        ebias[tid] = sel4(g, bias_f, bias_i, bias_c, bias_o)[j];
        ebu[tid]   = g_bu[g][j];
        eaw[tid]   = (j < IN_SZ) ? g_aw[g][j] : 0.f;
    }

    auto loadStage = [&](int kb, int st) {
        uint32_t sb = sbase + G2_HDR + st * G2_SSTR;
        const h16* Th = g_Th + (size_t)(by * 64) * 512 + kb * 32;
#pragma unroll
        for (int i = 0; i < 4; ++i) {
            int id = tid + i * 256;              // 1024: g(4) x row(64) x cc(4)
            int g = id >> 8, rem = id & 255;
            int row = rem >> 2, cc = rem & 3;
            size_t so = (size_t)row * 512 + g * 128 + cc * 8;
            uint32_t doff = (uint32_t)(g * 5120 + row * 80 + cc * 16);
            CP16(sb + doff, (const void*)(Th + so));
        }
#pragma unroll
        for (int i = 0; i < 4; ++i) {
            int id = tid + i * 256;              // g(4) x n(64) x cc(4)
            int g = id >> 8, rem = id & 255;
            int n = rem >> 2, cc = rem & 3;
            size_t so = ((size_t)g * 1024 + bx * 64 + n) * 128 + kb * 32 + cc * 8;
            uint32_t doff = (uint32_t)(20480 + g * 5120 + n * 80 + cc * 16);
            CP16(sb + doff, (const void*)(g_W2 + so));
        }
    };

    float acc[4][4][4];
#pragma unroll
    for (int a = 0; a < 4; ++a)
#pragma unroll
        for (int b = 0; b < 4; ++b)
#pragma unroll
            for (int q = 0; q < 4; ++q) acc[a][b][q] = 0.f;

    loadStage(0, 0);
    CPC();
    for (int kb = 0; kb < 4; ++kb) {
        int st = kb & 1;
        cpwait<0>();
        __syncthreads();
        if (kb < 3) {
            loadStage(kb + 1, st ^ 1);
            CPC();
        }

        uint32_t sb = sbase + G2_HDR + st * G2_SSTR;
        const int arow = m0 + (lane & 7) + ((lane >> 3) & 1) * 8;
        const int bnr = n0w + ((lane >> 4) << 3) + (lane & 7);
#pragma unroll
        for (int g = 0; g < 4; ++g) {
#pragma unroll
            for (int ks = 0; ks < 2; ++ks) {
                const int akc = ks * 16 + (lane >> 4) * 8;
                const int bkc = ks * 16 + ((lane >> 3) & 1) * 8;
                uint32_t ah[4], bb[2][4];
                uint32_t ad = sb + (uint32_t)((g * 2560 + arow * 40 + akc) * 2);
                ldsm4(ah, ad);
#pragma unroll
                for (int nh = 0; nh < 2; ++nh) {
                    uint32_t bd = sb + (uint32_t)((10240 + g * 2560 + (bnr + nh * 16) * 40 + bkc) * 2);
                    ldsm4(bb[nh], bd);
                }
#pragma unroll
                for (int nf = 0; nf < 4; ++nf) {
                    uint32_t b0 = bb[nf >> 1][(nf & 1) * 2], b1 = bb[nf >> 1][(nf & 1) * 2 + 1];
                    mma_f16(acc[g][nf], ah, b0, b1);
                }
            }
        }
    }

    // in-register LSTM epilogue
    const int r0 = m0 + (lane >> 2);
    const int jcb = n0w + (lane & 3) * 2;
    const bool hasx = (bx * 64 < IN_SZ);
    const size_t GS = (size_t)B_SZ * H_SZ;
#pragma unroll
    for (int nf = 0; nf < 4; ++nf) {
        int jl = jcb + nf * 8;
        int j = bx * 64 + jl;
#pragma unroll
        for (int rr = 0; rr < 2; ++rr) {
            int b = by * 64 + r0 + rr * 8;
            float2 h2 = *(const float2*)(h + (size_t)b * 1024 + j);
            float2 c2 = *(const float2*)(c + (size_t)b * 1024 + j);
            float2 x2 = hasx ? *(const float2*)(x + (size_t)b * IN_SZ + j) : make_float2(0.f, 0.f);
            float pr[4][2];
#pragma unroll
            for (int g = 0; g < 4; ++g) {
                pr[g][0] = acc[g][nf][rr * 2 + 0] + ebias[g * 64 + jl]     + h2.x * ebu[g * 64 + jl]     + x2.x * eaw[g * 64 + jl];
                pr[g][1] = acc[g][nf][rr * 2 + 1] + ebias[g * 64 + jl + 1] + h2.y * ebu[g * 64 + jl + 1] + x2.y * eaw[g * 64 + jl + 1];
            }
            float2 hn, cn;
            {
                float f = sigf(pr[0][0]), ii = sigf(pr[1][0]), gg = tanhfast(pr[2][0]), o = sigf(pr[3][0]);
                cn.x = f * c2.x + ii * gg;
                hn.x = o * tanhfast(cn.x);
            }
            {
                float f = sigf(pr[0][1]), ii = sigf(pr[1][1]), gg = tanhfast(pr[2][1]), o = sigf(pr[3][1]);
                cn.y = f * c2.y + ii * gg;
                hn.y = o * tanhfast(cn.y);
            }
            *(float2*)(out + (size_t)b * 1024 + j)      = hn;
            *(float2*)(out + GS + (size_t)b * 1024 + j) = cn;
        }
    }
}

// ---------------- launch ----------------
extern "C" void kernel_launch(void* const* d_in, const int* in_sizes, int n_in,
                              void* d_out, int out_size) {
    const float* x = (const float*)d_in[0];
    const float* h = (const float*)d_in[1];
    const float* c = (const float*)d_in[2];
    const float* Wu_f = (const float*)d_in[3];
    const float* Wu_i = (const float*)d_in[4];
    const float* Wu_c = (const float*)d_in[5];
    const float* Wu_o = (const float*)d_in[6];
    const float* Uu_f = (const float*)d_in[7];
    const float* Uu_i = (const float*)d_in[8];
    const float* Uu_c = (const float*)d_in[9];
    const float* Uu_o = (const float*)d_in[10];
    const float* Wf = (const float*)d_in[11];
    const float* Wi = (const float*)d_in[12];
    const float* Wc = (const float*)d_in[13];
    const float* Wo = (const float*)d_in[14];
    const float* Uf = (const float*)d_in[15];
    const float* Ui = (const float*)d_in[16];
    const float* Uc = (const float*)d_in[17];
    const float* Uo = (const float*)d_in[18];
    const float* bias_f = (const float*)d_in[19];
    const float* bias_i = (const float*)d_in[20];
    const float* bias_c = (const float*)d_in[21];
    const float* bias_o = (const float*)d_in[22];
    const float* W_dia = (const float*)d_in[23];
    const float* U_dia = (const float*)d_in[24];
    float* out = (float*)d_out;

    h16 *pW1x, *pW1h;
    cudaGetSymbolAddress((void**)&pW1x, g_W1x);
    cudaGetSymbolAddress((void**)&pW1h, g_W1h);

    cudaFuncSetAttribute(gemm1_hmma, cudaFuncAttributeMaxDynamicSharedMemorySize, G1_SMEM);
    cudaFuncSetAttribute(gemm2_hmma, cudaFuncAttributeMaxDynamicSharedMemorySize, G2_SMEM);

    prep_all<<<1072, 256>>>(Wu_f, Wu_i, Wu_c, Wu_o, Uu_f, Uu_i, Uu_c, Uu_o,
                            Wf, Wi, Wc, Wo, Uf, Ui, Uc, Uo, W_dia, U_dia);

    gemm1_hmma<<<dim3(2, B_SZ / 64), 256, G1_SMEM>>>(x, h, pW1x, pW1h);

    gemm2_hmma<<<dim3(H_SZ / 64, B_SZ / 64), 256, G2_SMEM>>>(
        x, h, c, bias_f, bias_i, bias_c, bias_o, out);
}